// round 5
// baseline (speedup 1.0000x reference)
#include <cuda_runtime.h>
#include <cuda_bf16.h>
#include <math.h>

#define NN   4096
#define FF   256
#define KH   4
#define FPH  64
#define MAXNB 128

// ---------------- scratch (device globals; no allocations) ----------------
__device__ __align__(16) float  g_xp[NN * FF];       // x @ W + b
__device__ __align__(16) float  g_src[NN * KH];      // per-node left scores
__device__ __align__(16) float  g_tgt[NN * KH];      // per-node right scores
__device__ double               g_partials[1024];    // [0..511] sum, [512..1023] sumsq
__device__ float                g_stats[2];          // mu, 1/sigma
__device__ unsigned short       g_adj[NN * MAXNB];   // neighbor lists
__device__ int                  g_cnt[NN];           // neighbor counts

// ---------------- K1: GEMM xp = x @ W + b  (64x64 tile, 4x4 microtile) ----
#define BM 64
#define BN 64
#define BK 16
__global__ __launch_bounds__(256) void gemm_kernel(const float* __restrict__ A,
                                                   const float* __restrict__ B,
                                                   const float* __restrict__ bias) {
    __shared__ float As[BK][BM + 4];   // transposed, padded
    __shared__ float Bs[BK][BN];
    const int tid = threadIdx.x;
    const int tx = tid & 15, ty = tid >> 4;
    const int row0 = blockIdx.y * BM;
    const int col0 = blockIdx.x * BN;

    float acc[4][4];
#pragma unroll
    for (int i = 0; i < 4; i++)
#pragma unroll
        for (int j = 0; j < 4; j++) acc[i][j] = 0.f;

    const int ar = tid >> 4, ak = tid & 15;   // A-tile loader coords
    const int bc = tid & 63, bk = tid >> 6;   // B-tile loader coords

    for (int k0 = 0; k0 < FF; k0 += BK) {
#pragma unroll
        for (int i = 0; i < 4; i++)
            As[ak][ar + i * 16] = A[(size_t)(row0 + ar + i * 16) * FF + (k0 + ak)];
#pragma unroll
        for (int i = 0; i < 4; i++)
            Bs[bk + i * 4][bc] = B[(size_t)(k0 + bk + i * 4) * FF + (col0 + bc)];
        __syncthreads();
#pragma unroll
        for (int kk = 0; kk < BK; kk++) {
            float4 av = *(const float4*)&As[kk][ty * 4];
            float4 bv = *(const float4*)&Bs[kk][tx * 4];
            float a[4] = {av.x, av.y, av.z, av.w};
            float b[4] = {bv.x, bv.y, bv.z, bv.w};
#pragma unroll
            for (int i = 0; i < 4; i++)
#pragma unroll
                for (int j = 0; j < 4; j++) acc[i][j] = fmaf(a[i], b[j], acc[i][j]);
        }
        __syncthreads();
    }
#pragma unroll
    for (int i = 0; i < 4; i++) {
        int r = row0 + ty * 4 + i;
#pragma unroll
        for (int j = 0; j < 4; j++) {
            int c = col0 + tx * 4 + j;
            g_xp[(size_t)r * FF + c] = acc[i][j] + bias[c];
        }
    }
}

// ---------------- K2: per-node head scores (one warp per (n,k)) ----------
__global__ __launch_bounds__(256) void score_kernel(const float* __restrict__ a_left,
                                                    const float* __restrict__ a_right) {
    __shared__ float sal[256], sar[256];
    sal[threadIdx.x] = a_left[threadIdx.x];
    sar[threadIdx.x] = a_right[threadIdx.x];
    __syncthreads();

    int wid  = blockIdx.x * 8 + (threadIdx.x >> 5);  // 0..16383
    int lane = threadIdx.x & 31;
    int n = wid >> 2, k = wid & 3;

    const float* row = g_xp + (size_t)n * FF + k * FPH;
    float x0 = row[lane], x1 = row[lane + 32];
    float s = x0 * sal[k * FPH + lane] + x1 * sal[k * FPH + lane + 32];
    float t = x0 * sar[k * FPH + lane] + x1 * sar[k * FPH + lane + 32];
#pragma unroll
    for (int off = 16; off > 0; off >>= 1) {
        s += __shfl_down_sync(0xffffffffu, s, off);
        t += __shfl_down_sync(0xffffffffu, t, off);
    }
    if (lane == 0) { g_src[n * 4 + k] = s; g_tgt[n * 4 + k] = t; }
}

// ---------------- K3: sum / sumsq of lrelu(src_i + tgt_j) over N*N*K -----
__global__ __launch_bounds__(256) void meanvar_kernel() {
    __shared__ float4 stgt4[1024];            // 1024 j's x 4 heads
    __shared__ double sred[256], qred[256];
    const int tid = threadIdx.x;
    const int rowbase = blockIdx.x * 8;

    float s[8][4];
#pragma unroll
    for (int i = 0; i < 8; i++) {
        float4 v = *(const float4*)&g_src[(rowbase + i) * 4];
        s[i][0] = v.x; s[i][1] = v.y; s[i][2] = v.z; s[i][3] = v.w;
    }

    float sum = 0.f, sq = 0.f;
    for (int jc = 0; jc < 4; jc++) {
        const float4* tg = (const float4*)(g_tgt + jc * 4096);
        for (int idx = tid; idx < 1024; idx += 256) stgt4[idx] = tg[idx];
        __syncthreads();
        for (int j = tid; j < 1024; j += 256) {
            float4 t4 = stgt4[j];
            float t[4] = {t4.x, t4.y, t4.z, t4.w};
#pragma unroll
            for (int i = 0; i < 8; i++) {
#pragma unroll
                for (int k = 0; k < 4; k++) {
                    float v = s[i][k] + t[k];
                    float z = fmaxf(v, 0.2f * v);     // leaky_relu(0.2)
                    sum += z;
                    sq = fmaf(z, z, sq);
                }
            }
        }
        __syncthreads();
    }
    sred[tid] = (double)sum; qred[tid] = (double)sq;
    __syncthreads();
    for (int off = 128; off > 0; off >>= 1) {
        if (tid < off) { sred[tid] += sred[tid + off]; qred[tid] += qred[tid + off]; }
        __syncthreads();
    }
    if (tid == 0) { g_partials[blockIdx.x] = sred[0]; g_partials[512 + blockIdx.x] = qred[0]; }
}

// ---------------- K4: finalize mu, 1/sigma --------------------------------
__global__ __launch_bounds__(256) void finalize_kernel() {
    __shared__ double sred[256], qred[256];
    const int tid = threadIdx.x;
    double a = 0.0, b = 0.0;
    for (int i = tid; i < 512; i += 256) { a += g_partials[i]; b += g_partials[512 + i]; }
    sred[tid] = a; qred[tid] = b;
    __syncthreads();
    for (int off = 128; off > 0; off >>= 1) {
        if (tid < off) { sred[tid] += sred[tid + off]; qred[tid] += qred[tid + off]; }
        __syncthreads();
    }
    if (tid == 0) {
        double n   = (double)NN * (double)NN * (double)KH;
        double mu  = sred[0] / n;
        double var = (qred[0] - sred[0] * sred[0] / n) / (n - 1.0);  // ddof=1
        g_stats[0] = (float)mu;
        g_stats[1] = (float)(1.0 / sqrt(var));
    }
}

// ---------------- K5: mask -> adjacency lists (one warp per row) ---------
__global__ __launch_bounds__(256) void adj_kernel(const float* __restrict__ mask) {
    int row  = blockIdx.x * 8 + (threadIdx.x >> 5);
    int lane = threadIdx.x & 31;
    const float4* r4 = (const float4*)(mask + (size_t)row * NN);
    unsigned short* adj = g_adj + (size_t)row * MAXNB;
    int count = 0;
    for (int it = 0; it < 32; it++) {
        float4 v = r4[it * 32 + lane];
        float vals[4] = {v.x, v.y, v.z, v.w};
        int jbase = it * 128 + lane * 4;
#pragma unroll
        for (int c = 0; c < 4; c++) {
            bool p = (vals[c] != 0.f);
            unsigned bal = __ballot_sync(0xffffffffu, p);
            if (p) {
                int pos = count + __popc(bal & ((1u << lane) - 1u));
                if (pos < MAXNB) adj[pos] = (unsigned short)(jbase + c);
            }
            count += __popc(bal);
        }
    }
    if (lane == 0) g_cnt[row] = min(count, MAXNB);
}

// ---------------- K6: fused softmax-denominator + aggregation + ELU ------
__global__ __launch_bounds__(256) void aggregate_kernel(float* __restrict__ out) {
    const int n = blockIdx.x;
    const int t = threadIdx.x;
    const int k = t >> 6;                 // head

    __shared__ unsigned short nb[MAXNB];
    __shared__ int   scnt;
    __shared__ float smu, sinv;

    if (t == 0) { scnt = g_cnt[n]; smu = g_stats[0]; sinv = g_stats[1]; }
    if (t < MAXNB) nb[t] = g_adj[(size_t)n * MAXNB + t];
    __syncthreads();

    const int   cnt = scnt;
    const float snk = g_src[n * 4 + k];
    const float mu = smu, inv = sinv;

    float acc = 0.f, wsum = 0.f;
    for (int e = 0; e < cnt; e++) {
        int m = nb[e];
        float v = snk + g_tgt[m * 4 + k];
        float z = fmaxf(v, 0.2f * v);                    // leaky_relu
        float w = __expf((z - mu) * inv);                // normalized + exp
        wsum += w;
        acc = fmaf(w, g_xp[(size_t)m * FF + t], acc);
    }
    float h = acc / wsum;
    out[(size_t)n * FF + t] = (h > 0.f) ? h : expm1f(h);  // ELU
}

// ---------------- launch ---------------------------------------------------
extern "C" void kernel_launch(void* const* d_in, const int* in_sizes, int n_in,
                              void* d_out, int out_size) {
    const float* x       = (const float*)d_in[0];
    const float* mask    = (const float*)d_in[1];
    // d_in[2] = batch (unused)
    const float* W       = (const float*)d_in[3];
    const float* b       = (const float*)d_in[4];
    const float* a_left  = (const float*)d_in[5];
    const float* a_right = (const float*)d_in[6];
    float* out = (float*)d_out;

    gemm_kernel<<<dim3(FF / BN, NN / BM), 256>>>(x, W, b);
    score_kernel<<<(NN * KH) / 8, 256>>>(a_left, a_right);
    meanvar_kernel<<<512, 256>>>();
    finalize_kernel<<<1, 256>>>();
    adj_kernel<<<NN / 8, 256>>>(mask);
    aggregate_kernel<<<NN, 256>>>(out);
}

// round 6
// speedup vs baseline: 1.0027x; 1.0027x over previous
#include <cuda_runtime.h>
#include <cuda_bf16.h>
#include <math.h>

#define NN   4096
#define FF   256
#define KH   4
#define FPH  64
#define MAXNB 128

// ---------------- scratch (device globals; no allocations) ----------------
__device__ __align__(16) float  g_xp[NN * FF];       // x @ W + b
__device__ __align__(16) float  g_src[NN * KH];      // per-node left scores
__device__ __align__(16) float  g_tgt[NN * KH];      // per-node right scores
__device__ double               g_partials[1024];    // [0..511] sum, [512..1023] sumsq
__device__ float                g_stats[2];          // mu, 1/sigma
__device__ unsigned short       g_adj[NN * MAXNB];   // neighbor lists
__device__ int                  g_cnt[NN];           // neighbor counts

// ---------------- K1: GEMM xp = x @ W + b  (64x64 tile, 4x4 microtile) ----
#define BM 64
#define BN 64
#define BK 16
__global__ __launch_bounds__(256) void gemm_kernel(const float* __restrict__ A,
                                                   const float* __restrict__ B,
                                                   const float* __restrict__ bias) {
    __shared__ float As[BK][BM + 4];   // transposed, padded
    __shared__ float Bs[BK][BN];
    const int tid = threadIdx.x;
    const int tx = tid & 15, ty = tid >> 4;
    const int row0 = blockIdx.y * BM;
    const int col0 = blockIdx.x * BN;

    float acc[4][4];
#pragma unroll
    for (int i = 0; i < 4; i++)
#pragma unroll
        for (int j = 0; j < 4; j++) acc[i][j] = 0.f;

    const int ar = tid >> 4, ak = tid & 15;   // A-tile loader coords
    const int bc = tid & 63, bk = tid >> 6;   // B-tile loader coords

    for (int k0 = 0; k0 < FF; k0 += BK) {
#pragma unroll
        for (int i = 0; i < 4; i++)
            As[ak][ar + i * 16] = A[(size_t)(row0 + ar + i * 16) * FF + (k0 + ak)];
#pragma unroll
        for (int i = 0; i < 4; i++)
            Bs[bk + i * 4][bc] = B[(size_t)(k0 + bk + i * 4) * FF + (col0 + bc)];
        __syncthreads();
#pragma unroll
        for (int kk = 0; kk < BK; kk++) {
            float4 av = *(const float4*)&As[kk][ty * 4];
            float4 bv = *(const float4*)&Bs[kk][tx * 4];
            float a[4] = {av.x, av.y, av.z, av.w};
            float b[4] = {bv.x, bv.y, bv.z, bv.w};
#pragma unroll
            for (int i = 0; i < 4; i++)
#pragma unroll
                for (int j = 0; j < 4; j++) acc[i][j] = fmaf(a[i], b[j], acc[i][j]);
        }
        __syncthreads();
    }
#pragma unroll
    for (int i = 0; i < 4; i++) {
        int r = row0 + ty * 4 + i;
#pragma unroll
        for (int j = 0; j < 4; j++) {
            int c = col0 + tx * 4 + j;
            g_xp[(size_t)r * FF + c] = acc[i][j] + bias[c];
        }
    }
}

// ---------------- K2: per-node head scores (one warp per (n,k)) ----------
__global__ __launch_bounds__(256) void score_kernel(const float* __restrict__ a_left,
                                                    const float* __restrict__ a_right) {
    __shared__ float sal[256], sar[256];
    sal[threadIdx.x] = a_left[threadIdx.x];
    sar[threadIdx.x] = a_right[threadIdx.x];
    __syncthreads();

    int wid  = blockIdx.x * 8 + (threadIdx.x >> 5);  // 0..16383
    int lane = threadIdx.x & 31;
    int n = wid >> 2, k = wid & 3;

    const float* row = g_xp + (size_t)n * FF + k * FPH;
    float x0 = row[lane], x1 = row[lane + 32];
    float s = x0 * sal[k * FPH + lane] + x1 * sal[k * FPH + lane + 32];
    float t = x0 * sar[k * FPH + lane] + x1 * sar[k * FPH + lane + 32];
#pragma unroll
    for (int off = 16; off > 0; off >>= 1) {
        s += __shfl_down_sync(0xffffffffu, s, off);
        t += __shfl_down_sync(0xffffffffu, t, off);
    }
    if (lane == 0) { g_src[n * 4 + k] = s; g_tgt[n * 4 + k] = t; }
}

// ---------------- K3: sum / sumsq of lrelu(src_i + tgt_j) over N*N*K -----
__global__ __launch_bounds__(256) void meanvar_kernel() {
    __shared__ float4 stgt4[1024];            // 1024 j's x 4 heads
    __shared__ double sred[256], qred[256];
    const int tid = threadIdx.x;
    const int rowbase = blockIdx.x * 8;

    float s[8][4];
#pragma unroll
    for (int i = 0; i < 8; i++) {
        float4 v = *(const float4*)&g_src[(rowbase + i) * 4];
        s[i][0] = v.x; s[i][1] = v.y; s[i][2] = v.z; s[i][3] = v.w;
    }

    float sum = 0.f, sq = 0.f;
    for (int jc = 0; jc < 4; jc++) {
        const float4* tg = (const float4*)(g_tgt + jc * 4096);
        for (int idx = tid; idx < 1024; idx += 256) stgt4[idx] = tg[idx];
        __syncthreads();
        for (int j = tid; j < 1024; j += 256) {
            float4 t4 = stgt4[j];
            float t[4] = {t4.x, t4.y, t4.z, t4.w};
#pragma unroll
            for (int i = 0; i < 8; i++) {
#pragma unroll
                for (int k = 0; k < 4; k++) {
                    float v = s[i][k] + t[k];
                    float z = fmaxf(v, 0.2f * v);     // leaky_relu(0.2)
                    sum += z;
                    sq = fmaf(z, z, sq);
                }
            }
        }
        __syncthreads();
    }
    sred[tid] = (double)sum; qred[tid] = (double)sq;
    __syncthreads();
    for (int off = 128; off > 0; off >>= 1) {
        if (tid < off) { sred[tid] += sred[tid + off]; qred[tid] += qred[tid + off]; }
        __syncthreads();
    }
    if (tid == 0) { g_partials[blockIdx.x] = sred[0]; g_partials[512 + blockIdx.x] = qred[0]; }
}

// ---------------- K4: finalize mu, 1/sigma --------------------------------
__global__ __launch_bounds__(256) void finalize_kernel() {
    __shared__ double sred[256], qred[256];
    const int tid = threadIdx.x;
    double a = 0.0, b = 0.0;
    for (int i = tid; i < 512; i += 256) { a += g_partials[i]; b += g_partials[512 + i]; }
    sred[tid] = a; qred[tid] = b;
    __syncthreads();
    for (int off = 128; off > 0; off >>= 1) {
        if (tid < off) { sred[tid] += sred[tid + off]; qred[tid] += qred[tid + off]; }
        __syncthreads();
    }
    if (tid == 0) {
        double n   = (double)NN * (double)NN * (double)KH;
        double mu  = sred[0] / n;
        double var = (qred[0] - sred[0] * sred[0] / n) / (n - 1.0);  // ddof=1
        g_stats[0] = (float)mu;
        g_stats[1] = (float)(1.0 / sqrt(var));
    }
}

// ---------------- K5: mask -> adjacency lists (one warp per row) ---------
__global__ __launch_bounds__(256) void adj_kernel(const float* __restrict__ mask) {
    int row  = blockIdx.x * 8 + (threadIdx.x >> 5);
    int lane = threadIdx.x & 31;
    const float4* r4 = (const float4*)(mask + (size_t)row * NN);
    unsigned short* adj = g_adj + (size_t)row * MAXNB;
    int count = 0;
    for (int it = 0; it < 32; it++) {
        float4 v = r4[it * 32 + lane];
        float vals[4] = {v.x, v.y, v.z, v.w};
        int jbase = it * 128 + lane * 4;
#pragma unroll
        for (int c = 0; c < 4; c++) {
            bool p = (vals[c] != 0.f);
            unsigned bal = __ballot_sync(0xffffffffu, p);
            if (p) {
                int pos = count + __popc(bal & ((1u << lane) - 1u));
                if (pos < MAXNB) adj[pos] = (unsigned short)(jbase + c);
            }
            count += __popc(bal);
        }
    }
    if (lane == 0) g_cnt[row] = min(count, MAXNB);
}

// ---------------- K6: fused softmax-denominator + aggregation + ELU ------
__global__ __launch_bounds__(256) void aggregate_kernel(float* __restrict__ out) {
    const int n = blockIdx.x;
    const int t = threadIdx.x;
    const int k = t >> 6;                 // head

    __shared__ unsigned short nb[MAXNB];
    __shared__ int   scnt;
    __shared__ float smu, sinv;

    if (t == 0) { scnt = g_cnt[n]; smu = g_stats[0]; sinv = g_stats[1]; }
    if (t < MAXNB) nb[t] = g_adj[(size_t)n * MAXNB + t];
    __syncthreads();

    const int   cnt = scnt;
    const float snk = g_src[n * 4 + k];
    const float mu = smu, inv = sinv;

    float acc = 0.f, wsum = 0.f;
    for (int e = 0; e < cnt; e++) {
        int m = nb[e];
        float v = snk + g_tgt[m * 4 + k];
        float z = fmaxf(v, 0.2f * v);                    // leaky_relu
        float w = __expf((z - mu) * inv);                // normalized + exp
        wsum += w;
        acc = fmaf(w, g_xp[(size_t)m * FF + t], acc);
    }
    float h = acc / wsum;
    out[(size_t)n * FF + t] = (h > 0.f) ? h : expm1f(h);  // ELU
}

// ---------------- launch ---------------------------------------------------
extern "C" void kernel_launch(void* const* d_in, const int* in_sizes, int n_in,
                              void* d_out, int out_size) {
    const float* x       = (const float*)d_in[0];
    const float* mask    = (const float*)d_in[1];
    // d_in[2] = batch (unused)
    const float* W       = (const float*)d_in[3];
    const float* b       = (const float*)d_in[4];
    const float* a_left  = (const float*)d_in[5];
    const float* a_right = (const float*)d_in[6];
    float* out = (float*)d_out;

    gemm_kernel<<<dim3(FF / BN, NN / BM), 256>>>(x, W, b);
    score_kernel<<<(NN * KH) / 8, 256>>>(a_left, a_right);
    meanvar_kernel<<<512, 256>>>();
    finalize_kernel<<<1, 256>>>();
    adj_kernel<<<NN / 8, 256>>>(mask);
    aggregate_kernel<<<NN, 256>>>(out);
}

// round 7
// speedup vs baseline: 1.0071x; 1.0044x over previous
#include <cuda_runtime.h>
#include <cuda_bf16.h>
#include <math.h>

#define NN   4096
#define FF   256
#define KH   4
#define FPH  64
#define MAXNB 128

// ---------------- scratch (device globals; no allocations) ----------------
__device__ __align__(16) float  g_xp[NN * FF];       // x @ W + b
__device__ __align__(16) float  g_src[NN * KH];      // per-node left scores
__device__ __align__(16) float  g_tgt[NN * KH];      // per-node right scores
__device__ double               g_partials[1024];    // [0..511] sum, [512..1023] sumsq
__device__ float                g_stats[2];          // mu, 1/sigma
__device__ unsigned short       g_adj[NN * MAXNB];   // neighbor lists
__device__ int                  g_cnt[NN];           // neighbor counts

// ---------------- K1: GEMM xp = x @ W + b  (64x64 tile, 4x4 microtile) ----
#define BM 64
#define BN 64
#define BK 16
__global__ __launch_bounds__(256) void gemm_kernel(const float* __restrict__ A,
                                                   const float* __restrict__ B,
                                                   const float* __restrict__ bias) {
    __shared__ float As[BK][BM + 4];   // transposed, padded
    __shared__ float Bs[BK][BN];
    const int tid = threadIdx.x;
    const int tx = tid & 15, ty = tid >> 4;
    const int row0 = blockIdx.y * BM;
    const int col0 = blockIdx.x * BN;

    float acc[4][4];
#pragma unroll
    for (int i = 0; i < 4; i++)
#pragma unroll
        for (int j = 0; j < 4; j++) acc[i][j] = 0.f;

    const int ar = tid >> 4, ak = tid & 15;   // A-tile loader coords
    const int bc = tid & 63, bk = tid >> 6;   // B-tile loader coords

    for (int k0 = 0; k0 < FF; k0 += BK) {
#pragma unroll
        for (int i = 0; i < 4; i++)
            As[ak][ar + i * 16] = A[(size_t)(row0 + ar + i * 16) * FF + (k0 + ak)];
#pragma unroll
        for (int i = 0; i < 4; i++)
            Bs[bk + i * 4][bc] = B[(size_t)(k0 + bk + i * 4) * FF + (col0 + bc)];
        __syncthreads();
#pragma unroll
        for (int kk = 0; kk < BK; kk++) {
            float4 av = *(const float4*)&As[kk][ty * 4];
            float4 bv = *(const float4*)&Bs[kk][tx * 4];
            float a[4] = {av.x, av.y, av.z, av.w};
            float b[4] = {bv.x, bv.y, bv.z, bv.w};
#pragma unroll
            for (int i = 0; i < 4; i++)
#pragma unroll
                for (int j = 0; j < 4; j++) acc[i][j] = fmaf(a[i], b[j], acc[i][j]);
        }
        __syncthreads();
    }
#pragma unroll
    for (int i = 0; i < 4; i++) {
        int r = row0 + ty * 4 + i;
#pragma unroll
        for (int j = 0; j < 4; j++) {
            int c = col0 + tx * 4 + j;
            g_xp[(size_t)r * FF + c] = acc[i][j] + bias[c];
        }
    }
}

// ---------------- K2: per-node head scores (one warp per (n,k)) ----------
__global__ __launch_bounds__(256) void score_kernel(const float* __restrict__ a_left,
                                                    const float* __restrict__ a_right) {
    __shared__ float sal[256], sar[256];
    sal[threadIdx.x] = a_left[threadIdx.x];
    sar[threadIdx.x] = a_right[threadIdx.x];
    __syncthreads();

    int wid  = blockIdx.x * 8 + (threadIdx.x >> 5);  // 0..16383
    int lane = threadIdx.x & 31;
    int n = wid >> 2, k = wid & 3;

    const float* row = g_xp + (size_t)n * FF + k * FPH;
    float x0 = row[lane], x1 = row[lane + 32];
    float s = x0 * sal[k * FPH + lane] + x1 * sal[k * FPH + lane + 32];
    float t = x0 * sar[k * FPH + lane] + x1 * sar[k * FPH + lane + 32];
#pragma unroll
    for (int off = 16; off > 0; off >>= 1) {
        s += __shfl_down_sync(0xffffffffu, s, off);
        t += __shfl_down_sync(0xffffffffu, t, off);
    }
    if (lane == 0) { g_src[n * 4 + k] = s; g_tgt[n * 4 + k] = t; }
}

// ---------------- K3: sum / sumsq of lrelu(src_i + tgt_j) over N*N*K -----
__global__ __launch_bounds__(256) void meanvar_kernel() {
    __shared__ float4 stgt4[1024];            // 1024 j's x 4 heads
    __shared__ double sred[256], qred[256];
    const int tid = threadIdx.x;
    const int rowbase = blockIdx.x * 8;

    float s[8][4];
#pragma unroll
    for (int i = 0; i < 8; i++) {
        float4 v = *(const float4*)&g_src[(rowbase + i) * 4];
        s[i][0] = v.x; s[i][1] = v.y; s[i][2] = v.z; s[i][3] = v.w;
    }

    float sum = 0.f, sq = 0.f;
    for (int jc = 0; jc < 4; jc++) {
        const float4* tg = (const float4*)(g_tgt + jc * 4096);
        for (int idx = tid; idx < 1024; idx += 256) stgt4[idx] = tg[idx];
        __syncthreads();
        for (int j = tid; j < 1024; j += 256) {
            float4 t4 = stgt4[j];
            float t[4] = {t4.x, t4.y, t4.z, t4.w};
#pragma unroll
            for (int i = 0; i < 8; i++) {
#pragma unroll
                for (int k = 0; k < 4; k++) {
                    float v = s[i][k] + t[k];
                    float z = fmaxf(v, 0.2f * v);     // leaky_relu(0.2)
                    sum += z;
                    sq = fmaf(z, z, sq);
                }
            }
        }
        __syncthreads();
    }
    sred[tid] = (double)sum; qred[tid] = (double)sq;
    __syncthreads();
    for (int off = 128; off > 0; off >>= 1) {
        if (tid < off) { sred[tid] += sred[tid + off]; qred[tid] += qred[tid + off]; }
        __syncthreads();
    }
    if (tid == 0) { g_partials[blockIdx.x] = sred[0]; g_partials[512 + blockIdx.x] = qred[0]; }
}

// ---------------- K4: finalize mu, 1/sigma --------------------------------
__global__ __launch_bounds__(256) void finalize_kernel() {
    __shared__ double sred[256], qred[256];
    const int tid = threadIdx.x;
    double a = 0.0, b = 0.0;
    for (int i = tid; i < 512; i += 256) { a += g_partials[i]; b += g_partials[512 + i]; }
    sred[tid] = a; qred[tid] = b;
    __syncthreads();
    for (int off = 128; off > 0; off >>= 1) {
        if (tid < off) { sred[tid] += sred[tid + off]; qred[tid] += qred[tid + off]; }
        __syncthreads();
    }
    if (tid == 0) {
        double n   = (double)NN * (double)NN * (double)KH;
        double mu  = sred[0] / n;
        double var = (qred[0] - sred[0] * sred[0] / n) / (n - 1.0);  // ddof=1
        g_stats[0] = (float)mu;
        g_stats[1] = (float)(1.0 / sqrt(var));
    }
}

// ---------------- K5: mask -> adjacency lists (one warp per row) ---------
__global__ __launch_bounds__(256) void adj_kernel(const float* __restrict__ mask) {
    int row  = blockIdx.x * 8 + (threadIdx.x >> 5);
    int lane = threadIdx.x & 31;
    const float4* r4 = (const float4*)(mask + (size_t)row * NN);
    unsigned short* adj = g_adj + (size_t)row * MAXNB;
    int count = 0;
    for (int it = 0; it < 32; it++) {
        float4 v = r4[it * 32 + lane];
        float vals[4] = {v.x, v.y, v.z, v.w};
        int jbase = it * 128 + lane * 4;
#pragma unroll
        for (int c = 0; c < 4; c++) {
            bool p = (vals[c] != 0.f);
            unsigned bal = __ballot_sync(0xffffffffu, p);
            if (p) {
                int pos = count + __popc(bal & ((1u << lane) - 1u));
                if (pos < MAXNB) adj[pos] = (unsigned short)(jbase + c);
            }
            count += __popc(bal);
        }
    }
    if (lane == 0) g_cnt[row] = min(count, MAXNB);
}

// ---------------- K6: fused softmax-denominator + aggregation + ELU ------
__global__ __launch_bounds__(256) void aggregate_kernel(float* __restrict__ out) {
    const int n = blockIdx.x;
    const int t = threadIdx.x;
    const int k = t >> 6;                 // head

    __shared__ unsigned short nb[MAXNB];
    __shared__ int   scnt;
    __shared__ float smu, sinv;

    if (t == 0) { scnt = g_cnt[n]; smu = g_stats[0]; sinv = g_stats[1]; }
    if (t < MAXNB) nb[t] = g_adj[(size_t)n * MAXNB + t];
    __syncthreads();

    const int   cnt = scnt;
    const float snk = g_src[n * 4 + k];
    const float mu = smu, inv = sinv;

    float acc = 0.f, wsum = 0.f;
    for (int e = 0; e < cnt; e++) {
        int m = nb[e];
        float v = snk + g_tgt[m * 4 + k];
        float z = fmaxf(v, 0.2f * v);                    // leaky_relu
        float w = __expf((z - mu) * inv);                // normalized + exp
        wsum += w;
        acc = fmaf(w, g_xp[(size_t)m * FF + t], acc);
    }
    float h = acc / wsum;
    out[(size_t)n * FF + t] = (h > 0.f) ? h : expm1f(h);  // ELU
}

// ---------------- launch ---------------------------------------------------
extern "C" void kernel_launch(void* const* d_in, const int* in_sizes, int n_in,
                              void* d_out, int out_size) {
    const float* x       = (const float*)d_in[0];
    const float* mask    = (const float*)d_in[1];
    // d_in[2] = batch (unused)
    const float* W       = (const float*)d_in[3];
    const float* b       = (const float*)d_in[4];
    const float* a_left  = (const float*)d_in[5];
    const float* a_right = (const float*)d_in[6];
    float* out = (float*)d_out;

    gemm_kernel<<<dim3(FF / BN, NN / BM), 256>>>(x, W, b);
    score_kernel<<<(NN * KH) / 8, 256>>>(a_left, a_right);
    meanvar_kernel<<<512, 256>>>();
    finalize_kernel<<<1, 256>>>();
    adj_kernel<<<NN / 8, 256>>>(mask);
    aggregate_kernel<<<NN, 256>>>(out);
}